// round 1
// baseline (speedup 1.0000x reference)
#include <cuda_runtime.h>
#include <cuda_bf16.h>

// Upsample2d (up=2, binomial 4-tap) == separable linear-phase interp:
//   out[2m]   = 0.25*x[m-1] + 0.75*x[m]
//   out[2m+1] = 0.75*x[m]   + 0.25*x[m+1]
// applied in x then y (zero-padded boundaries).

#define W_IN  128
#define H_IN  128
#define W_OUT 256
#define H_OUT 256
#define RPT   32     // input rows per thread strip
#define TPX   64     // threads in x: each owns 2 input cols -> 4 output cols
#define TPY   4      // strips per block: TPY*RPT == H_IN

__global__ __launch_bounds__(TPX * TPY)
void Upsample_63797444215162_kernel(const float* __restrict__ x,
                                    float* __restrict__ out) {
    const int tx   = threadIdx.x;        // 0..63 : column pair
    const int n0   = threadIdx.y * RPT;  // strip start row
    const int img  = blockIdx.x;         // B*C images

    const float* __restrict__ xi = x   + (size_t)img * (H_IN * W_IN);
    float*       __restrict__ oi = out + (size_t)img * (H_OUT * W_OUT);

    const int c0 = 2 * tx;               // input col base
    const int oc = 4 * tx;               // output col base
    const bool has_l = (tx > 0);
    const bool has_r = (tx < TPX - 1);

    // h(n) = horizontal interp of input row n at the 4 output columns
    float hE0p, hO0p, hE1p, hO1p;        // h(n-1), rolled

    if (n0 == 0) {
        hE0p = hO0p = hE1p = hO1p = 0.0f;
    } else {
        const float* row = xi + (n0 - 1) * W_IN;
        float  a  = has_l ? __ldg(row + c0 - 1) : 0.0f;
        float2 bc = *reinterpret_cast<const float2*>(row + c0);
        float  d  = has_r ? __ldg(row + c0 + 2) : 0.0f;
        hE0p = 0.25f * a    + 0.75f * bc.x;
        hO0p = 0.75f * bc.x + 0.25f * bc.y;
        hE1p = 0.25f * bc.x + 0.75f * bc.y;
        hO1p = 0.75f * bc.y + 0.25f * d;
    }

    const int n1 = n0 + RPT;
    #pragma unroll 4
    for (int n = n0; n < n1; ++n) {
        const float* row = xi + n * W_IN;
        float  a  = has_l ? __ldg(row + c0 - 1) : 0.0f;
        float2 bc = *reinterpret_cast<const float2*>(row + c0);
        float  d  = has_r ? __ldg(row + c0 + 2) : 0.0f;

        float hE0 = 0.25f * a    + 0.75f * bc.x;
        float hO0 = 0.75f * bc.x + 0.25f * bc.y;
        float hE1 = 0.25f * bc.x + 0.75f * bc.y;
        float hO1 = 0.75f * bc.y + 0.25f * d;

        // out row 2n-1: 0.75*h(n-1) + 0.25*h(n)   (row -1 doesn't exist)
        if (n > 0) {
            float4 o;
            o.x = 0.75f * hE0p + 0.25f * hE0;
            o.y = 0.75f * hO0p + 0.25f * hO0;
            o.z = 0.75f * hE1p + 0.25f * hE1;
            o.w = 0.75f * hO1p + 0.25f * hO1;
            *reinterpret_cast<float4*>(oi + (2 * n - 1) * W_OUT + oc) = o;
        }
        // out row 2n: 0.25*h(n-1) + 0.75*h(n)
        {
            float4 o;
            o.x = 0.25f * hE0p + 0.75f * hE0;
            o.y = 0.25f * hO0p + 0.75f * hO0;
            o.z = 0.25f * hE1p + 0.75f * hE1;
            o.w = 0.25f * hO1p + 0.75f * hO1;
            *reinterpret_cast<float4*>(oi + (2 * n) * W_OUT + oc) = o;
        }

        hE0p = hE0; hO0p = hO0; hE1p = hE1; hO1p = hO1;
    }

    // last output row 2H-1 = 0.75*h(H-1) (h(H)=0), owned by the last strip
    if (n1 == H_IN) {
        float4 o;
        o.x = 0.75f * hE0p;
        o.y = 0.75f * hO0p;
        o.z = 0.75f * hE1p;
        o.w = 0.75f * hO1p;
        *reinterpret_cast<float4*>(oi + (H_OUT - 1) * W_OUT + oc) = o;
    }
}

extern "C" void kernel_launch(void* const* d_in, const int* in_sizes, int n_in,
                              void* d_out, int out_size) {
    const float* x = (const float*)d_in[0];   // [8,128,128,128] fp32
    // d_in[1] is the 4x4 binomial kernel; fixed => weights folded into code.
    float* out = (float*)d_out;               // [8,128,256,256] fp32

    const int n_img = in_sizes[0] / (H_IN * W_IN);   // B*C = 1024
    dim3 block(TPX, TPY);
    dim3 grid(n_img);
    Upsample_63797444215162_kernel<<<grid, block>>>(x, out);
}

// round 2
// speedup vs baseline: 1.1136x; 1.1136x over previous
#include <cuda_runtime.h>
#include <cuda_bf16.h>

// Upsample2d (up=2, binomial 4-tap) == separable linear-phase interp:
//   out[2m]   = 0.25*x[m-1] + 0.75*x[m]
//   out[2m+1] = 0.75*x[m]   + 0.25*x[m+1]
// applied in x then y (zero-padded boundaries).
//
// R2: batched 8-row loads (MLP=8), shfl halo exchange, streaming stores.

#define W_IN  128
#define H_IN  128
#define W_OUT 256
#define H_OUT 256
#define RPT   32     // input rows per thread strip
#define TPX   64     // threads in x: each owns 2 input cols -> 4 output cols
#define TPY   4      // strips per block: TPY*RPT == H_IN
#define CHUNK 8      // rows loaded per prefetch batch

__device__ __forceinline__ void store4_cs(float* p, float a, float b, float c, float d) {
    float4 v = make_float4(a, b, c, d);
    __stcs(reinterpret_cast<float4*>(p), v);
}

__global__ __launch_bounds__(TPX * TPY)
void Upsample_63797444215162_kernel(const float* __restrict__ x,
                                    float* __restrict__ out) {
    const int tx   = threadIdx.x;        // 0..63 : column pair
    const int n0   = threadIdx.y * RPT;  // strip start row
    const int img  = blockIdx.x;         // B*C images

    const float* __restrict__ xi = x   + (size_t)img * (H_IN * W_IN);
    float*       __restrict__ oi = out + (size_t)img * (H_OUT * W_OUT);

    const int c0   = 2 * tx;             // input col base
    const int oc   = 4 * tx;             // output col base
    const int lane = tx & 31;
    const bool seam_l = (lane == 0)  && (tx > 0);        // needs scalar halo load
    const bool seam_r = (lane == 31) && (tx < TPX - 1);
    const bool edge_l = (tx == 0);
    const bool edge_r = (tx == TPX - 1);

    // h(n-1) rolled across iterations
    float hE0p, hO0p, hE1p, hO1p;

    if (n0 == 0) {
        hE0p = hO0p = hE1p = hO1p = 0.0f;
    } else {
        const float* row = xi + (n0 - 1) * W_IN;
        float2 bc = *reinterpret_cast<const float2*>(row + c0);
        float a = __shfl_up_sync(0xffffffffu, bc.y, 1);
        if (lane == 0) a = seam_l ? __ldg(row + c0 - 1) : 0.0f;
        float d = __shfl_down_sync(0xffffffffu, bc.x, 1);
        if (lane == 31) d = seam_r ? __ldg(row + c0 + 2) : 0.0f;
        if (edge_l) a = 0.0f;
        if (edge_r) d = 0.0f;
        hE0p = 0.25f * a    + 0.75f * bc.x;
        hO0p = 0.75f * bc.x + 0.25f * bc.y;
        hE1p = 0.25f * bc.x + 0.75f * bc.y;
        hO1p = 0.75f * bc.y + 0.25f * d;
    }

    const int n1 = n0 + RPT;
    for (int base = n0; base < n1; base += CHUNK) {
        // batched loads: 8 independent LDG.64 in flight
        float2 v[CHUNK];
        #pragma unroll
        for (int k = 0; k < CHUNK; ++k) {
            v[k] = *reinterpret_cast<const float2*>(xi + (base + k) * W_IN + c0);
        }

        #pragma unroll
        for (int k = 0; k < CHUNK; ++k) {
            const int n = base + k;
            float2 bc = v[k];
            float a = __shfl_up_sync(0xffffffffu, bc.y, 1);
            if (lane == 0) a = seam_l ? __ldg(xi + n * W_IN + c0 - 1) : 0.0f;
            float d = __shfl_down_sync(0xffffffffu, bc.x, 1);
            if (lane == 31) d = seam_r ? __ldg(xi + n * W_IN + c0 + 2) : 0.0f;
            if (edge_l) a = 0.0f;
            if (edge_r) d = 0.0f;

            float hE0 = 0.25f * a    + 0.75f * bc.x;
            float hO0 = 0.75f * bc.x + 0.25f * bc.y;
            float hE1 = 0.25f * bc.x + 0.75f * bc.y;
            float hO1 = 0.75f * bc.y + 0.25f * d;

            // out row 2n-1 = 0.75*h(n-1) + 0.25*h(n)
            if (n > 0) {
                store4_cs(oi + (2 * n - 1) * W_OUT + oc,
                          0.75f * hE0p + 0.25f * hE0,
                          0.75f * hO0p + 0.25f * hO0,
                          0.75f * hE1p + 0.25f * hE1,
                          0.75f * hO1p + 0.25f * hO1);
            }
            // out row 2n = 0.25*h(n-1) + 0.75*h(n)
            store4_cs(oi + (2 * n) * W_OUT + oc,
                      0.25f * hE0p + 0.75f * hE0,
                      0.25f * hO0p + 0.75f * hO0,
                      0.25f * hE1p + 0.75f * hE1,
                      0.25f * hO1p + 0.75f * hO1);

            hE0p = hE0; hO0p = hO0; hE1p = hE1; hO1p = hO1;
        }
    }

    // last output row 2H-1 = 0.75*h(H-1), owned by the last strip
    if (n1 == H_IN) {
        store4_cs(oi + (H_OUT - 1) * W_OUT + oc,
                  0.75f * hE0p, 0.75f * hO0p, 0.75f * hE1p, 0.75f * hO1p);
    }
}

extern "C" void kernel_launch(void* const* d_in, const int* in_sizes, int n_in,
                              void* d_out, int out_size) {
    const float* x = (const float*)d_in[0];   // [8,128,128,128] fp32
    // d_in[1] is the 4x4 binomial kernel; fixed => weights folded into code.
    float* out = (float*)d_out;               // [8,128,256,256] fp32

    const int n_img = in_sizes[0] / (H_IN * W_IN);   // B*C = 1024
    dim3 block(TPX, TPY);
    dim3 grid(n_img);
    Upsample_63797444215162_kernel<<<grid, block>>>(x, out);
}